// round 4
// baseline (speedup 1.0000x reference)
#include <cuda_runtime.h>
#include <cstdint>

#define DEVINL __device__ __forceinline__

// Problem constants
static const int Bb = 4, Ss = 4096, Dd = 1024, Hh = 16;

// Scratch (static device globals — allocation-free)
__device__ __align__(128) float g_qkv[16384 * 3072];  // 192 MB [tokens, 3D]
__device__ __align__(128) float g_ao[16384 * 1024];   // 64 MB  [tokens, D]

// ---------------------------------------------------------------------------
// helpers
// ---------------------------------------------------------------------------
DEVINL uint32_t f2tf32(float f) {
    uint32_t u;
    asm("cvt.rna.tf32.f32 %0, %1;" : "=r"(u) : "f"(f));
    return u;
}
DEVINL void mma_tf32(float* c, const uint32_t* a, uint32_t b0, uint32_t b1) {
    asm("mma.sync.aligned.m16n8k8.row.col.f32.tf32.tf32.f32 "
        "{%0,%1,%2,%3}, {%4,%5,%6,%7}, {%8,%9}, {%0,%1,%2,%3};"
        : "+f"(c[0]), "+f"(c[1]), "+f"(c[2]), "+f"(c[3])
        : "r"(a[0]), "r"(a[1]), "r"(a[2]), "r"(a[3]), "r"(b0), "r"(b1));
}
DEVINL uint32_t smem_u32(const void* p) { return (uint32_t)__cvta_generic_to_shared(p); }
DEVINL void cp16(uint32_t dst, const void* src) {
    asm volatile("cp.async.ca.shared.global [%0], [%1], 16;" :: "r"(dst), "l"(src));
}
DEVINL void cp_commit() { asm volatile("cp.async.commit_group;"); }
template<int N> DEVINL void cp_wait() { asm volatile("cp.async.wait_group %0;" :: "n"(N)); }

// Fragment-major tf32 layouts (block stride 132 floats = 33*16B, bank-rotating):
//  A-layout: element (r,c): blk=(r>>4)*KK8+(c>>3); lane=(r&7)*4+(c&3);
//            i = ((r>>3)&1) + 2*((c>>2)&1).  float addr = blk*132 + lane*4 + i.
//            Thread frag read: one LDS.128 at blk*132+lane*4 -> {a0,a1,a2,a3}.
//  B-layout: element (n,c): blk=(n>>4)*KK8+(c>>3); lane=(n&7)*4+(c&3);
//            i = 2*((n>>3)&1) + ((c>>2)&1).  One LDS.128 -> {b0e,b1e,b0o,b1o}
//            (even/odd n8 blocks of the n16 block).

// ---------------------------------------------------------------------------
// Projection GEMM: C[M,N] = A[M,K] @ W[N,K]^T + bias[N]
// BM=256, BN=128, BK=32. 8 warps, warp tile 64x64.
// LDG-prefetch -> cvt -> fragment-major STS, double buffered.
// smem/buffer: fragA 64 blk *132 = 8448 f, fragB 32 blk *132 = 4224 f.
// ---------------------------------------------------------------------------
__global__ void __launch_bounds__(256, 1)
gemm_proj(const float* __restrict__ A, int lda,
          const float* __restrict__ W, int ldw,
          float* __restrict__ C, int ldc,
          int K, const float* __restrict__ bias)
{
    extern __shared__ float sm[];
    const int tid = threadIdx.x, lane = tid & 31, wid = tid >> 5;
    const int wm16 = (wid & 3) * 4;    // first m16 block of warp
    const int wn16 = (wid >> 2) * 4;   // first n16 block of warp
    const long long m0 = (long long)blockIdx.y * 256;
    const long long n0 = (long long)blockIdx.x * 128;

    float acc[4][4][2][4] = {};   // [im][in2][sub][4]
    float4 pf[12];

    auto ldg_tile = [&](int it) {
        const long long k0 = (long long)it * 32;
        #pragma unroll
        for (int i = 0; i < 8; ++i) {
            int lin = i * 256 + tid; int r = lin >> 3, c4 = (lin & 7) * 4;
            pf[i] = *(const float4*)&A[(m0 + r) * lda + k0 + c4];
        }
        #pragma unroll
        for (int i = 0; i < 4; ++i) {
            int lin = i * 256 + tid; int r = lin >> 3, c4 = (lin & 7) * 4;
            pf[8 + i] = *(const float4*)&W[(n0 + r) * ldw + k0 + c4];
        }
    };
    auto sts_tile = [&](int buf) {
        float* fA = sm + buf * 12672;
        float* fB = fA + 8448;
        #pragma unroll
        for (int i = 0; i < 8; ++i) {
            int lin = i * 256 + tid; int r = lin >> 3, c4 = (lin & 7) * 4;
            int blk = (r >> 4) * 4 + (c4 >> 3);
            uint32_t* d = (uint32_t*)(fA + blk * 132 + (r & 7) * 16
                                      + ((r >> 3) & 1) + 2 * ((c4 >> 2) & 1));
            d[0] = f2tf32(pf[i].x); d[4] = f2tf32(pf[i].y);
            d[8] = f2tf32(pf[i].z); d[12] = f2tf32(pf[i].w);
        }
        #pragma unroll
        for (int i = 0; i < 4; ++i) {
            int lin = i * 256 + tid; int r = lin >> 3, c4 = (lin & 7) * 4;
            int blk = (r >> 4) * 4 + (c4 >> 3);
            uint32_t* d = (uint32_t*)(fB + blk * 132 + (r & 7) * 16
                                      + 2 * ((r >> 3) & 1) + ((c4 >> 2) & 1));
            d[0] = f2tf32(pf[8 + i].x); d[4] = f2tf32(pf[8 + i].y);
            d[8] = f2tf32(pf[8 + i].z); d[12] = f2tf32(pf[8 + i].w);
        }
    };

    const int NIT = K / 32;
    ldg_tile(0);
    int buf = 0;
    for (int it = 0; it < NIT; ++it) {
        sts_tile(buf);
        if (it + 1 < NIT) ldg_tile(it + 1);
        __syncthreads();
        const float* fA = sm + buf * 12672;
        const float* fB = fA + 8448;
        #pragma unroll
        for (int kk8 = 0; kk8 < 4; ++kk8) {
            uint4 a[4], b[4];
            #pragma unroll
            for (int im = 0; im < 4; ++im)
                a[im] = *(const uint4*)&fA[((wm16 + im) * 4 + kk8) * 132 + lane * 4];
            #pragma unroll
            for (int in2 = 0; in2 < 4; ++in2)
                b[in2] = *(const uint4*)&fB[((wn16 + in2) * 4 + kk8) * 132 + lane * 4];
            #pragma unroll
            for (int in2 = 0; in2 < 4; ++in2)
                #pragma unroll
                for (int im = 0; im < 4; ++im) {
                    mma_tf32(acc[im][in2][0], (const uint32_t*)&a[im], b[in2].x, b[in2].y);
                    mma_tf32(acc[im][in2][1], (const uint32_t*)&a[im], b[in2].z, b[in2].w);
                }
        }
        buf ^= 1;
    }

    #pragma unroll
    for (int im = 0; im < 4; ++im) {
        long long r = m0 + (wm16 + im) * 16 + (lane >> 2);
        #pragma unroll
        for (int in2 = 0; in2 < 4; ++in2)
            #pragma unroll
            for (int sub = 0; sub < 2; ++sub) {
                long long c = n0 + (wn16 + in2) * 16 + sub * 8 + 2 * (lane & 3);
                float b0 = bias[c], b1 = bias[c + 1];
                const float* v = acc[im][in2][sub];
                *(float2*)&C[r * ldc + c]       = make_float2(v[0] + b0, v[1] + b1);
                *(float2*)&C[(r + 8) * ldc + c] = make_float2(v[2] + b0, v[3] + b1);
            }
    }
}

// ---------------------------------------------------------------------------
// Fused attention, fragment-major tf32.
// smem floats: fQ 8448 | fK 8448 | fV 8448 | fP 8448 | rawK 8192 | rawV 8192
// total 50176 f = 200704 B. Per (win,head), 128 Q-rows/CTA, key chunks of 128.
// ---------------------------------------------------------------------------
__global__ void __launch_bounds__(256, 1)
attn_fused(const float* __restrict__ qkv, float* __restrict__ ao, int W, int nc)
{
    extern __shared__ float sm[];
    float* fQ = sm;
    float* fK = sm + 8448;
    float* fV = sm + 16896;
    float* fP = sm + 25344;
    float* rawK = sm + 33792;
    float* rawV = sm + 41984;

    const int tid = threadIdx.x, lane = tid & 31, wid = tid >> 5;
    const int pair = blockIdx.y;
    const int win = pair >> 4, h = pair & 15;
    const int q0 = blockIdx.x * 128;
    const long long base = (long long)win * W * 3072 + h * 64;
    const float* Qg = qkv + base + (long long)q0 * 3072;
    const float* Kg = qkv + base + 1024;
    const float* Vg = qkv + base + 2048;

    // issue Q (into rawV, group) then K0 (into rawK, group)
    #pragma unroll
    for (int i = 0; i < 8; ++i) {
        int lin = i * 256 + tid; int r = lin >> 4, c4 = (lin & 15) * 4;
        cp16(smem_u32(rawV + r * 64 + c4), Qg + (long long)r * 3072 + c4);
    }
    cp_commit();
    #pragma unroll
    for (int i = 0; i < 8; ++i) {
        int lin = i * 256 + tid; int r = lin >> 4, c4 = (lin & 15) * 4;
        cp16(smem_u32(rawK + r * 64 + c4), Kg + (long long)r * 3072 + c4);
    }
    cp_commit();
    cp_wait<1>();           // Q arrived
    __syncthreads();
    // convert Q -> fQ (A-layout, r=qrow, c=dim)
    #pragma unroll
    for (int i = 0; i < 8; ++i) {
        int lin = i * 256 + tid; int r = lin >> 4, c4 = (lin & 15) * 4;
        float4 v = *(const float4*)&rawV[r * 64 + c4];
        int blk = (r >> 4) * 8 + (c4 >> 3);
        uint32_t* d = (uint32_t*)(fQ + blk * 132 + (r & 7) * 16
                                  + ((r >> 3) & 1) + 2 * ((c4 >> 2) & 1));
        d[0] = f2tf32(v.x); d[4] = f2tf32(v.y); d[8] = f2tf32(v.z); d[12] = f2tf32(v.w);
    }
    __syncthreads();
    // issue V0 into rawV
    #pragma unroll
    for (int i = 0; i < 8; ++i) {
        int lin = i * 256 + tid; int r = lin >> 4, c4 = (lin & 15) * 4;
        cp16(smem_u32(rawV + r * 64 + c4), Vg + (long long)r * 3072 + c4);
    }
    cp_commit();            // pending: {K0, V0}

    float oacc[8][4] = {};
    float m_[2] = {-1e30f, -1e30f}, l_[2] = {0.f, 0.f};
    const int rw0 = q0 + wid * 16 + (lane >> 2);

    for (int c = 0; c < nc; ++c) {
        const bool more = (c + 1 < nc);
        cp_wait<1>();       // K_c arrived (oldest pending)
        __syncthreads();
        // convert K -> fK (B-layout, n=key, c=dim)
        #pragma unroll
        for (int i = 0; i < 8; ++i) {
            int lin = i * 256 + tid; int r = lin >> 4, c4 = (lin & 15) * 4;
            float4 v = *(const float4*)&rawK[r * 64 + c4];
            int blk = (r >> 4) * 8 + (c4 >> 3);
            uint32_t* d = (uint32_t*)(fK + blk * 132 + (r & 7) * 16
                                      + 2 * ((r >> 3) & 1) + ((c4 >> 2) & 1));
            d[0] = f2tf32(v.x); d[4] = f2tf32(v.y); d[8] = f2tf32(v.z); d[12] = f2tf32(v.w);
        }
        __syncthreads();    // fK ready; rawK free
        if (more) {
            const float* Kc = Kg + (long long)(c + 1) * 128 * 3072;
            #pragma unroll
            for (int i = 0; i < 8; ++i) {
                int lin = i * 256 + tid; int r = lin >> 4, c4 = (lin & 15) * 4;
                cp16(smem_u32(rawK + r * 64 + c4), Kc + (long long)r * 3072 + c4);
            }
            cp_commit();
        }

        // ---- S = Q K^T ----
        float sacc[16][4];
        #pragma unroll
        for (int i = 0; i < 16; ++i)
            sacc[i][0] = sacc[i][1] = sacc[i][2] = sacc[i][3] = 0.f;
        #pragma unroll
        for (int kk8 = 0; kk8 < 8; ++kk8) {
            uint4 a = *(const uint4*)&fQ[(wid * 8 + kk8) * 132 + lane * 4];
            #pragma unroll
            for (int n16 = 0; n16 < 8; ++n16) {
                uint4 b = *(const uint4*)&fK[(n16 * 8 + kk8) * 132 + lane * 4];
                mma_tf32(sacc[2 * n16],     (const uint32_t*)&a, b.x, b.y);
                mma_tf32(sacc[2 * n16 + 1], (const uint32_t*)&a, b.z, b.w);
            }
        }

        // V arrival + convert (B-layout, n=dim, c=key)
        if (more) cp_wait<1>(); else cp_wait<0>();
        __syncthreads();
        #pragma unroll
        for (int i = 0; i < 8; ++i) {
            int lin = i * 256 + tid; int r = lin >> 4, c4 = (lin & 15) * 4;
            float4 v = *(const float4*)&rawV[r * 64 + c4];
            int blk = (c4 >> 4) * 16 + (r >> 3);
            int off0 = ((c4 & 7) * 4 + (r & 3)) * 4
                       + 2 * ((c4 >> 3) & 1) + ((r >> 2) & 1);
            uint32_t* d = (uint32_t*)(fV + blk * 132);
            d[off0] = f2tf32(v.x); d[off0 + 16] = f2tf32(v.y);
            d[off0 + 32] = f2tf32(v.z); d[off0 + 48] = f2tf32(v.w);
        }
        __syncthreads();    // fV ready; rawV free
        if (more) {
            const float* Vc = Vg + (long long)(c + 1) * 128 * 3072;
            #pragma unroll
            for (int i = 0; i < 8; ++i) {
                int lin = i * 256 + tid; int r = lin >> 4, c4 = (lin & 15) * 4;
                cp16(smem_u32(rawV + r * 64 + c4), Vc + (long long)r * 3072 + c4);
            }
            cp_commit();
        }

        // ---- online softmax (ADDITIVE +1.0 mask for col > row) ----
        float scale0 = 0.f, scale1 = 0.f;
        #pragma unroll
        for (int hh = 0; hh < 2; ++hh) {
            const int rw = rw0 + hh * 8;
            float cm = -1e30f;
            #pragma unroll
            for (int in = 0; in < 16; ++in) {
                int col = c * 128 + in * 8 + 2 * (lane & 3);
                float v0 = sacc[in][2 * hh]     * 0.125f + ((col     > rw) ? 1.f : 0.f);
                float v1 = sacc[in][2 * hh + 1] * 0.125f + ((col + 1 > rw) ? 1.f : 0.f);
                sacc[in][2 * hh] = v0; sacc[in][2 * hh + 1] = v1;
                cm = fmaxf(cm, fmaxf(v0, v1));
            }
            cm = fmaxf(cm, __shfl_xor_sync(0xffffffffu, cm, 1));
            cm = fmaxf(cm, __shfl_xor_sync(0xffffffffu, cm, 2));
            float mn = fmaxf(m_[hh], cm);
            float sc = __expf(m_[hh] - mn);
            float rs = 0.f;
            #pragma unroll
            for (int in = 0; in < 16; ++in) {
                float p0 = __expf(sacc[in][2 * hh] - mn);
                float p1 = __expf(sacc[in][2 * hh + 1] - mn);
                sacc[in][2 * hh] = p0; sacc[in][2 * hh + 1] = p1;
                rs += p0 + p1;
            }
            rs += __shfl_xor_sync(0xffffffffu, rs, 1);
            rs += __shfl_xor_sync(0xffffffffu, rs, 2);
            l_[hh] = l_[hh] * sc + rs;
            m_[hh] = mn;
            if (hh == 0) scale0 = sc; else scale1 = sc;
        }
        #pragma unroll
        for (int in = 0; in < 8; ++in) {
            oacc[in][0] *= scale0; oacc[in][1] *= scale0;
            oacc[in][2] *= scale1; oacc[in][3] *= scale1;
        }

        // ---- O += P V, two key-halves through warp-private fP ----
        const int lp = (lane >> 2) * 4 + 2 * (lane & 1);
        const int i0 = 2 * ((lane & 3) >> 1);
        #pragma unroll
        for (int half = 0; half < 2; ++half) {
            #pragma unroll
            for (int kk8l = 0; kk8l < 8; ++kk8l) {
                int in = half * 8 + kk8l;
                uint32_t* bp = (uint32_t*)(fP + wid * 1056 + kk8l * 132);
                *(uint2*)(bp + lp * 4 + i0)       =
                    make_uint2(f2tf32(sacc[in][0]), f2tf32(sacc[in][2]));
                *(uint2*)(bp + (lp + 1) * 4 + i0) =
                    make_uint2(f2tf32(sacc[in][1]), f2tf32(sacc[in][3]));
            }
            __syncwarp();
            #pragma unroll
            for (int kk8l = 0; kk8l < 8; ++kk8l) {
                int kk8 = half * 8 + kk8l;
                uint4 a = *(const uint4*)&fP[wid * 1056 + kk8l * 132 + lane * 4];
                #pragma unroll
                for (int n16 = 0; n16 < 4; ++n16) {
                    uint4 b = *(const uint4*)&fV[(n16 * 16 + kk8) * 132 + lane * 4];
                    mma_tf32(oacc[2 * n16],     (const uint32_t*)&a, b.x, b.y);
                    mma_tf32(oacc[2 * n16 + 1], (const uint32_t*)&a, b.z, b.w);
                }
            }
            __syncwarp();
        }
        __syncthreads();    // fK/fV reuse safety for next chunk
    }

    // ---- epilogue ----
    const float inv0 = 1.f / l_[0], inv1 = 1.f / l_[1];
    const long long trow = (long long)win * W + q0 + wid * 16 + (lane >> 2);
    float* Od = ao + trow * 1024 + h * 64;
    #pragma unroll
    for (int in = 0; in < 8; ++in) {
        int cc = in * 8 + 2 * (lane & 3);
        *(float2*)&Od[cc]            = make_float2(oacc[in][0] * inv0, oacc[in][1] * inv0);
        *(float2*)&Od[8 * 1024 + cc] = make_float2(oacc[in][2] * inv1, oacc[in][3] * inv1);
    }
}

// ---------------------------------------------------------------------------
// driver
// ---------------------------------------------------------------------------
static const int PROJ_SMEM = 2 * 12672 * 4;   // 101376
static const int ATTN_SMEM = 50176 * 4;       // 200704

static void run_branch(const float* x, const float* w_in, const float* b_in,
                       const float* w_out, const float* b_out,
                       int W, float* out, float* qkv, float* ao)
{
    const int M = Bb * Ss;   // 16384
    gemm_proj<<<dim3(3072 / 128, M / 256), 256, PROJ_SMEM>>>(
        x, Dd, w_in, Dd, qkv, 3072, Dd, b_in);

    const int nwin = M / W;
    attn_fused<<<dim3(W / 128, nwin * Hh), 256, ATTN_SMEM>>>(qkv, ao, W, W / 128);

    gemm_proj<<<dim3(1024 / 128, M / 256), 256, PROJ_SMEM>>>(
        ao, Dd, w_out, Dd, out, Dd, Dd, b_out);
}

extern "C" void kernel_launch(void* const* d_in, const int* in_sizes, int n_in,
                              void* d_out, int out_size)
{
    const float* lqs    = (const float*)d_in[0];
    const float* gqs    = (const float*)d_in[1];
    const float* wl_in  = (const float*)d_in[2];
    const float* bl_in  = (const float*)d_in[3];
    const float* wl_out = (const float*)d_in[4];
    const float* bl_out = (const float*)d_in[5];
    const float* wg_in  = (const float*)d_in[6];
    const float* bg_in  = (const float*)d_in[7];
    const float* wg_out = (const float*)d_in[8];
    const float* bg_out = (const float*)d_in[9];
    float* out = (float*)d_out;

    cudaFuncSetAttribute(gemm_proj, cudaFuncAttributeMaxDynamicSharedMemorySize, PROJ_SMEM);
    cudaFuncSetAttribute(attn_fused, cudaFuncAttributeMaxDynamicSharedMemorySize, ATTN_SMEM);

    float *qkv, *ao;
    cudaGetSymbolAddress((void**)&qkv, g_qkv);
    cudaGetSymbolAddress((void**)&ao, g_ao);

    run_branch(lqs, wl_in, bl_in, wl_out, bl_out, 128, out, qkv, ao);
    run_branch(gqs, wg_in, bg_in, wg_out, bg_out, 1024,
               out + (size_t)Bb * Ss * Dd, qkv, ao);
}